// round 2
// baseline (speedup 1.0000x reference)
#include <cuda_runtime.h>
#include <math.h>

#define L   768
#define D   1024
#define DP  128
#define DP2 64
#define H   128
#define NB  64

#define TI 16
#define TJ 16
#define QK_PITCH 68   // 64 + pad; row stride 272B (16B aligned)
#define A_PITCH  132  // 128 + pad; row stride 528B (16B aligned)

typedef unsigned long long u64;

// ---- packed f32x2 helpers (sm_100+ PTX; FFMA2 path ptxas never auto-emits) ----
__device__ __forceinline__ u64 pack2(float lo, float hi) {
    u64 r; asm("mov.b64 %0, {%1,%2};" : "=l"(r) : "f"(lo), "f"(hi)); return r;
}
__device__ __forceinline__ void unpack2(u64 v, float& lo, float& hi) {
    asm("mov.b64 {%0,%1}, %2;" : "=f"(lo), "=f"(hi) : "l"(v));
}
__device__ __forceinline__ u64 fma2(u64 a, u64 b, u64 c) {
    u64 d; asm("fma.rn.f32x2 %0, %1, %2, %3;" : "=l"(d) : "l"(a), "l"(b), "l"(c)); return d;
}
__device__ __forceinline__ u64 add2(u64 a, u64 b) {
    u64 d; asm("add.rn.f32x2 %0, %1, %2;" : "=l"(d) : "l"(a), "l"(b)); return d;
}

// ---- device scratch (no allocations allowed) ----
__device__ float g_q [L * DP2];
__device__ float g_k [L * DP2];
__device__ float g_Aq[L * H];    // q @ W1b^T + b1
__device__ float g_Ak[L * H];    // k @ W1b^T

// ============================================================
// Kernel 0: downprojection  xd[l,p] = x[l,:] . W_down[p,:] + b_down[p]
// ============================================================
__global__ void down_kernel(const float* __restrict__ x,
                            const float* __restrict__ Wd,
                            const float* __restrict__ bd) {
    __shared__ float sx[D];
    const int l = blockIdx.x;
    const int p = threadIdx.x;             // 0..127

    const float4* xr  = (const float4*)(x + (size_t)l * D);
    float4*       sx4 = (float4*)sx;
    for (int i = p; i < D / 4; i += blockDim.x) sx4[i] = xr[i];
    __syncthreads();

    const float4* wr = (const float4*)(Wd + (size_t)p * D);
    float acc = bd[p];
    #pragma unroll 8
    for (int i = 0; i < D / 4; ++i) {
        float4 w  = wr[i];
        float4 xv = sx4[i];
        acc = fmaf(w.x, xv.x, acc);
        acc = fmaf(w.y, xv.y, acc);
        acc = fmaf(w.z, xv.z, acc);
        acc = fmaf(w.w, xv.w, acc);
    }
    if (p < DP2) g_q[l * DP2 + p]         = acc;
    else         g_k[l * DP2 + (p - DP2)] = acc;
}

// ============================================================
// Kernel 1: additive terms  Aq = q@W1b^T + b1 ; Ak = k@W1b^T
// ============================================================
__global__ void proj_kernel(const float* __restrict__ W1,
                            const float* __restrict__ b1) {
    __shared__ float sq[DP2], sk[DP2];
    const int l = blockIdx.x;
    const int h = threadIdx.x;             // 0..127

    if (h < DP2) sq[h]       = g_q[l * DP2 + h];
    else         sk[h - DP2] = g_k[l * DP2 + (h - DP2)];
    __syncthreads();

    const float* w = W1 + (size_t)h * DP + DP2;
    float aq = b1[h];
    float ak = 0.f;
    #pragma unroll 8
    for (int p = 0; p < DP2; ++p) {
        float wv = w[p];
        aq = fmaf(wv, sq[p], aq);
        ak = fmaf(wv, sk[p], ak);
    }
    g_Aq[l * H + h] = aq;
    g_Ak[l * H + h] = ak;
}

// ============================================================
// Main kernel: one thread == one (i,j) pair; CTA = 16x16 pair tile.
//   h1 = Aq[j] - Ak[i] + W1a @ (q[j] .* k[i])   (K=64, packed f32x2)
//   exact GELU -> LN (packed) -> out = h1n @ W2^T + b2 (packed f32x2)
// Fully unrolled -> constant register indexing, no local memory.
// Weight smem reads are uniform-address -> conflict-free broadcast LDS.128.
// ============================================================
extern __shared__ float smem[];

__global__ void __launch_bounds__(256, 1)
main_kernel(const float* __restrict__ W1,
            const float* __restrict__ lng,
            const float* __restrict__ lnb,
            const float* __restrict__ W2,
            const float* __restrict__ b2,
            float* __restrict__ out) {
    // ---- smem layout (all offsets 16B-aligned) ----
    float* sW1a = smem;                       // [p:64][h:128]  (transposed)
    float* sW2  = sW1a + DP2 * H;             // [h:128][n:64]  (transposed)
    float* sQ   = sW2  + H * NB;              // [TJ][QK_PITCH]
    float* sK   = sQ   + TJ * QK_PITCH;       // [TI][QK_PITCH]
    float* sAq  = sK   + TI * QK_PITCH;       // [TJ][A_PITCH]
    float* sAk  = sAq  + TJ * A_PITCH;        // [TI][A_PITCH]
    float* sLg  = sAk  + TI * A_PITCH;        // [128]
    float* sLb  = sLg  + H;                   // [128]
    float* sB2  = sLb  + H;                   // [64]

    const int tid = threadIdx.x;
    const int j0  = blockIdx.x * TJ;
    const int i0  = blockIdx.y * TI;

    // W1a transposed: sW1a[p*H + h] = W1[h*DP + p], p<64
    for (int idx = tid; idx < H * DP2; idx += 256) {
        int h = idx >> 6;
        int p = idx & 63;
        sW1a[p * H + h] = W1[h * DP + p];
    }
    // W2 transposed: sW2[h*NB + n] = W2[n*H + h]
    for (int idx = tid; idx < H * NB; idx += 256) {
        int n = idx >> 7;
        int h = idx & 127;
        sW2[h * NB + n] = W2[n * H + h];
    }
    for (int idx = tid; idx < TJ * DP2; idx += 256) {
        int r = idx >> 6;
        int p = idx & 63;
        sQ[r * QK_PITCH + p] = g_q[(j0 + r) * DP2 + p];
        sK[r * QK_PITCH + p] = g_k[(i0 + r) * DP2 + p];
    }
    for (int idx = tid; idx < TJ * H; idx += 256) {
        int r = idx >> 7;
        int h = idx & 127;
        sAq[r * A_PITCH + h] = g_Aq[(j0 + r) * H + h];
        sAk[r * A_PITCH + h] = g_Ak[(i0 + r) * H + h];
    }
    if (tid < H)            { sLg[tid] = lng[tid]; sLb[tid] = lnb[tid]; }
    else if (tid < H + NB)  { sB2[tid - H] = b2[tid - H]; }
    __syncthreads();

    const int tx = tid & 15;    // j within tile (q row)
    const int ty = tid >> 4;    // i within tile (k row)

    const u64 NEG1 = pack2(-1.0f, -1.0f);

    // ---- h1 init: Aq[j] - Ak[i]  (packed: aq + (-1)*ak) ----
    u64 h1[H / 2];
    {
        const u64* aq2 = (const u64*)(sAq + tx * A_PITCH);
        const u64* ak2 = (const u64*)(sAk + ty * A_PITCH);
        #pragma unroll
        for (int m = 0; m < H / 2; ++m)
            h1[m] = fma2(ak2[m], NEG1, aq2[m]);
    }

    // ---- GEMM1 (K=64), packed FFMA2; weights via broadcast LDS.128 ----
    const float* qrow = sQ + tx * QK_PITCH;
    const float* krow = sK + ty * QK_PITCH;
    #pragma unroll 2
    for (int p = 0; p < DP2; ++p) {
        const float qk = qrow[p] * krow[p];
        const u64 qk2 = pack2(qk, qk);
        const ulonglong2* w4 = (const ulonglong2*)(sW1a + p * H);  // uniform addr
        #pragma unroll
        for (int m4 = 0; m4 < H / 4; ++m4) {
            ulonglong2 w = w4[m4];
            h1[2 * m4 + 0] = fma2(w.x, qk2, h1[2 * m4 + 0]);
            h1[2 * m4 + 1] = fma2(w.y, qk2, h1[2 * m4 + 1]);
        }
    }

    // ---- exact GELU (scalar erf) + packed mean ----
    u64 mu2 = pack2(0.f, 0.f);
    #pragma unroll
    for (int m = 0; m < H / 2; ++m) {
        float a, b;
        unpack2(h1[m], a, b);
        a = a * normcdff(a);           // x * Phi(x): exact-erf GELU
        b = b * normcdff(b);
        h1[m] = pack2(a, b);
        mu2 = add2(mu2, h1[m]);
    }
    float mlo, mhi;
    unpack2(mu2, mlo, mhi);
    const float mu = (mlo + mhi) * (1.0f / H);

    // ---- packed variance ----
    const u64 nmu2 = pack2(-mu, -mu);
    u64 var2 = pack2(0.f, 0.f);
    #pragma unroll
    for (int m = 0; m < H / 2; ++m) {
        u64 d = add2(h1[m], nmu2);
        var2 = fma2(d, d, var2);
    }
    float vlo, vhi;
    unpack2(var2, vlo, vhi);
    const float rstd = rsqrtf((vlo + vhi) * (1.0f / H) + 1e-5f);

    // ---- packed LayerNorm: ((h1 - mu)*rstd)*g + b ----
    {
        const u64 r2 = pack2(rstd, rstd);
        const u64 c2 = pack2(-mu * rstd, -mu * rstd);
        const u64* g2 = (const u64*)sLg;
        const u64* bb = (const u64*)sLb;
        #pragma unroll
        for (int m = 0; m < H / 2; ++m) {
            u64 t = fma2(h1[m], r2, c2);     // (h1 - mu) * rstd
            h1[m] = fma2(t, g2[m], bb[m]);   // * g + b
        }
    }

    // ---- GEMM2 (128 -> 64), packed FFMA2 ----
    u64 acc[NB / 2];
    {
        const u64* bi = (const u64*)sB2;
        #pragma unroll
        for (int n = 0; n < NB / 2; ++n) acc[n] = bi[n];
    }
    #pragma unroll
    for (int m = 0; m < H / 2; ++m) {
        float v0, v1;
        unpack2(h1[m], v0, v1);
        const u64 v02 = pack2(v0, v0);
        const u64 v12 = pack2(v1, v1);
        const ulonglong2* wa = (const ulonglong2*)(sW2 + (2 * m + 0) * NB);
        const ulonglong2* wb = (const ulonglong2*)(sW2 + (2 * m + 1) * NB);
        #pragma unroll
        for (int n4 = 0; n4 < NB / 4; ++n4) {
            ulonglong2 w = wa[n4];
            acc[2 * n4 + 0] = fma2(w.x, v02, acc[2 * n4 + 0]);
            acc[2 * n4 + 1] = fma2(w.y, v02, acc[2 * n4 + 1]);
        }
        #pragma unroll
        for (int n4 = 0; n4 < NB / 4; ++n4) {
            ulonglong2 w = wb[n4];
            acc[2 * n4 + 0] = fma2(w.x, v12, acc[2 * n4 + 0]);
            acc[2 * n4 + 1] = fma2(w.y, v12, acc[2 * n4 + 1]);
        }
    }

    // ---- write out[i, j, :] (256B-aligned rows, 16B stores) ----
    ulonglong2* op = (ulonglong2*)(out + ((size_t)(i0 + ty) * L + (j0 + tx)) * NB);
    #pragma unroll
    for (int n4 = 0; n4 < NB / 4; ++n4) {
        ulonglong2 v;
        v.x = acc[2 * n4 + 0];
        v.y = acc[2 * n4 + 1];
        op[n4] = v;
    }
}

static const int MAIN_SMEM_BYTES =
    (DP2 * H + H * NB + TJ * QK_PITCH + TI * QK_PITCH +
     TJ * A_PITCH + TI * A_PITCH + H + H + NB) * (int)sizeof(float);

extern "C" void kernel_launch(void* const* d_in, const int* in_sizes, int n_in,
                              void* d_out, int out_size) {
    const float* x   = (const float*)d_in[0];
    const float* Wd  = (const float*)d_in[1];
    const float* bd  = (const float*)d_in[2];
    const float* W1  = (const float*)d_in[3];
    const float* b1  = (const float*)d_in[4];
    const float* lng = (const float*)d_in[5];
    const float* lnb = (const float*)d_in[6];
    const float* W2  = (const float*)d_in[7];
    const float* b2  = (const float*)d_in[8];
    float* out = (float*)d_out;

    cudaFuncSetAttribute(main_kernel,
                         cudaFuncAttributeMaxDynamicSharedMemorySize,
                         MAIN_SMEM_BYTES);

    down_kernel<<<L, 128>>>(x, Wd, bd);
    proj_kernel<<<L, 128>>>(W1, b1);
    main_kernel<<<dim3(L / TJ, L / TI), 256, MAIN_SMEM_BYTES>>>(
        W1, lng, lnb, W2, b2, out);
}

// round 3
// speedup vs baseline: 1.1233x; 1.1233x over previous
#include <cuda_runtime.h>
#include <math.h>

#define L   768
#define D   1024
#define DP  128
#define DP2 64
#define H   128
#define NB  64

#define TI 16
#define TJ 16
#define QK_PITCH 65    // conflict-free for tx-strided scalar reads (65 mod 32 = 1)
#define A_PITCH  130   // even (8B-aligned rows for u64 loads)

typedef unsigned long long u64;

// ---- packed f32x2 helpers (sm_100+; FFMA2 path ptxas never auto-emits) ----
__device__ __forceinline__ u64 pack2(float lo, float hi) {
    u64 r; asm("mov.b64 %0, {%1,%2};" : "=l"(r) : "f"(lo), "f"(hi)); return r;
}
__device__ __forceinline__ void unpack2(u64 v, float& lo, float& hi) {
    asm("mov.b64 {%0,%1}, %2;" : "=f"(lo), "=f"(hi) : "l"(v));
}
__device__ __forceinline__ u64 fma2(u64 a, u64 b, u64 c) {
    u64 d; asm("fma.rn.f32x2 %0, %1, %2, %3;" : "=l"(d) : "l"(a), "l"(b), "l"(c)); return d;
}
__device__ __forceinline__ u64 add2(u64 a, u64 b) {
    u64 d; asm("add.rn.f32x2 %0, %1, %2;" : "=l"(d) : "l"(a), "l"(b)); return d;
}

// ---- device scratch (no allocations allowed) ----
__device__ float g_q  [L * DP2];
__device__ float g_k  [L * DP2];
__device__ float g_Aq [L * H];      // q @ W1b^T + b1
__device__ float g_Ak [L * H];      // k @ W1b^T
__device__ float g_W2g[H * NB];     // [h][n] = W2[n,h] * ln_g[h]
__device__ float g_c1 [NB];         // sum_h W2[n,h] * ln_g[h]
__device__ float g_c2 [NB];         // sum_h W2[n,h] * ln_b[h] + b2[n]

// ============================================================
// Kernel 0 (blocks 0..95): down-projection + additive terms, 8 rows/CTA.
//   xd[l,p] = x[l,:].W_down[p,:] + b_down[p]  -> q,k
//   Aq[l,h] = q[l,:].W1b[h,:] + b1[h] ; Ak[l,h] = k[l,:].W1b[h,:]
// Block 96: epilogue constants W2g / c1 / c2.
// ============================================================
__global__ void __launch_bounds__(256, 1)
pre_kernel(const float* __restrict__ x,
           const float* __restrict__ Wd,
           const float* __restrict__ bd,
           const float* __restrict__ W1,
           const float* __restrict__ b1,
           const float* __restrict__ lng,
           const float* __restrict__ lnb,
           const float* __restrict__ W2,
           const float* __restrict__ b2) {
    const int tid = threadIdx.x;

    if (blockIdx.x == 96) {
        // ---- epilogue constants ----
        for (int idx = tid; idx < H * NB; idx += 256) {
            int h = idx >> 6;          // /64
            int n = idx & 63;
            g_W2g[idx] = W2[n * H + h] * lng[h];
        }
        if (tid < NB) {
            float c1 = 0.f, c2 = 0.f;
            for (int h = 0; h < H; ++h) {
                float w = W2[tid * H + h];
                c1 = fmaf(w, lng[h], c1);
                c2 = fmaf(w, lnb[h], c2);
            }
            g_c1[tid] = c1;
            g_c2[tid] = c2 + b2[tid];
        }
        return;
    }

    __shared__ float sx[8 * D];        // 32 KB; reused for xd after sync
    const int l0   = blockIdx.x * 8;
    const int p    = tid & 127;
    const int half = tid >> 7;         // 0..1 -> rows half*4 .. half*4+3

    // stage 8 rows of x
    {
        const float4* xr  = (const float4*)(x + (size_t)l0 * D);
        float4*       sx4 = (float4*)sx;
        #pragma unroll
        for (int it = 0; it < 8; ++it) sx4[tid + it * 256] = xr[tid + it * 256];
    }
    __syncthreads();

    // down-projection: 4 rows per thread, one p each
    float acc0 = bd[p], acc1 = acc0, acc2 = acc0, acc3 = acc0;
    {
        const float4* wr  = (const float4*)(Wd + (size_t)p * D);
        const float4* sx4 = (const float4*)(sx + (half * 4) * D);
        #pragma unroll 4
        for (int i = 0; i < D / 4; ++i) {
            float4 w = wr[i];
            float4 a = sx4[i];
            float4 b = sx4[i + 1 * (D / 4)];
            float4 c = sx4[i + 2 * (D / 4)];
            float4 d = sx4[i + 3 * (D / 4)];
            acc0 = fmaf(w.x, a.x, acc0); acc0 = fmaf(w.y, a.y, acc0);
            acc0 = fmaf(w.z, a.z, acc0); acc0 = fmaf(w.w, a.w, acc0);
            acc1 = fmaf(w.x, b.x, acc1); acc1 = fmaf(w.y, b.y, acc1);
            acc1 = fmaf(w.z, b.z, acc1); acc1 = fmaf(w.w, b.w, acc1);
            acc2 = fmaf(w.x, c.x, acc2); acc2 = fmaf(w.y, c.y, acc2);
            acc2 = fmaf(w.z, c.z, acc2); acc2 = fmaf(w.w, c.w, acc2);
            acc3 = fmaf(w.x, d.x, acc3); acc3 = fmaf(w.y, d.y, acc3);
            acc3 = fmaf(w.z, d.z, acc3); acc3 = fmaf(w.w, d.w, acc3);
        }
    }
    float accs[4] = {acc0, acc1, acc2, acc3};
    #pragma unroll
    for (int r = 0; r < 4; ++r) {
        int l = l0 + half * 4 + r;
        if (p < DP2) g_q[l * DP2 + p]         = accs[r];
        else         g_k[l * DP2 + (p - DP2)] = accs[r];
    }
    __syncthreads();
    // stash xd into smem (reuse sx)
    #pragma unroll
    for (int r = 0; r < 4; ++r) sx[(half * 4 + r) * DP + p] = accs[r];
    __syncthreads();

    // additive terms: thread h computes Aq/Ak for its 4 rows
    {
        const int h = tid & 127;
        const float* w = W1 + (size_t)h * DP + DP2;
        const float* xd = sx + (half * 4) * DP;
        float aq[4], ak[4];
        #pragma unroll
        for (int r = 0; r < 4; ++r) { aq[r] = b1[h]; ak[r] = 0.f; }
        #pragma unroll 4
        for (int pp = 0; pp < DP2; ++pp) {
            float wv = w[pp];
            #pragma unroll
            for (int r = 0; r < 4; ++r) {
                aq[r] = fmaf(wv, xd[r * DP + pp],       aq[r]);
                ak[r] = fmaf(wv, xd[r * DP + DP2 + pp], ak[r]);
            }
        }
        #pragma unroll
        for (int r = 0; r < 4; ++r) {
            int l = l0 + half * 4 + r;
            g_Aq[l * H + h] = aq[r];
            g_Ak[l * H + h] = ak[r];
        }
    }
}

// ============================================================
// Main kernel: one thread == one (i,j) pair; CTA = 16x16 pair tile.
// h processed in 4 chunks of 32 to bound live registers (~130 peak):
//   chunk GEMM1 -> fused GELU + GEMM2 streaming (h1 dies immediately).
// LN folded into epilogue constants:
//   out[n] = rstd*S[n] + (-rstd*mu)*c1[n] + c2[n]
// ============================================================
extern __shared__ float smem[];

__global__ void __launch_bounds__(256, 1)
main_kernel(const float* __restrict__ W1,
            float* __restrict__ out) {
    // ---- smem layout ----
    float* sW1a = smem;                       // [p:64][h:128]  (transposed)   32KB
    float* sW2g = sW1a + DP2 * H;             // [h:128][n:64]  (g folded)     32KB
    float* sQ   = sW2g + H * NB;              // [TJ][QK_PITCH]
    float* sK   = sQ   + TJ * QK_PITCH;       // [TI][QK_PITCH]
    float* sAq  = sK   + TI * QK_PITCH;       // [TJ][A_PITCH]
    float* sAk  = sAq  + TJ * A_PITCH;        // [TI][A_PITCH]
    float* sC1  = sAk  + TI * A_PITCH;        // [64]
    float* sC2  = sC1  + NB;                  // [64]

    const int tid = threadIdx.x;
    const int j0  = blockIdx.x * TJ;
    const int i0  = blockIdx.y * TI;

    // W1a transposed: sW1a[p*H + h] = W1[h*DP + p], p<64
    for (int idx = tid; idx < H * DP2; idx += 256) {
        int h = idx >> 6;
        int p = idx & 63;
        sW1a[p * H + h] = W1[h * DP + p];
    }
    for (int idx = tid; idx < H * NB; idx += 256) sW2g[idx] = g_W2g[idx];
    for (int idx = tid; idx < TJ * DP2; idx += 256) {
        int r = idx >> 6;
        int p = idx & 63;
        sQ[r * QK_PITCH + p] = g_q[(j0 + r) * DP2 + p];
        sK[r * QK_PITCH + p] = g_k[(i0 + r) * DP2 + p];
    }
    for (int idx = tid; idx < TJ * H; idx += 256) {
        int r = idx >> 7;
        int h = idx & 127;
        sAq[r * A_PITCH + h] = g_Aq[(j0 + r) * H + h];
        sAk[r * A_PITCH + h] = g_Ak[(i0 + r) * H + h];
    }
    if (tid < NB)                 sC1[tid]      = g_c1[tid];
    else if (tid < 2 * NB)        sC2[tid - NB] = g_c2[tid - NB];
    __syncthreads();

    const int tx = tid & 15;    // j within tile
    const int ty = tid >> 4;    // i within tile

    const u64 NEG1 = pack2(-1.0f, -1.0f);
    const float* qrow = sQ + tx * QK_PITCH;
    const float* krow = sK + ty * QK_PITCH;
    const u64*   aq2  = (const u64*)(sAq + tx * A_PITCH);
    const u64*   ak2  = (const u64*)(sAk + ty * A_PITCH);

    u64 S[NB / 2];                              // 32 u64 = 64 regs
    #pragma unroll
    for (int n = 0; n < NB / 2; ++n) S[n] = 0ULL;
    u64 sum2 = 0ULL, sq2 = 0ULL;

    #pragma unroll
    for (int c = 0; c < 4; ++c) {               // h-chunks of 32
        // ---- GEMM1 for this chunk: 16 u64 = 32 regs ----
        u64 hc[16];
        #pragma unroll
        for (int m = 0; m < 16; ++m)
            hc[m] = fma2(ak2[c * 16 + m], NEG1, aq2[c * 16 + m]);

        #pragma unroll 2
        for (int p = 0; p < DP2; ++p) {
            const float qk = qrow[p] * krow[p];
            const u64 qk2 = pack2(qk, qk);
            const ulonglong2* w4 =
                (const ulonglong2*)(sW1a + p * H + c * 32);   // uniform -> broadcast
            #pragma unroll
            for (int m4 = 0; m4 < 8; ++m4) {
                ulonglong2 w = w4[m4];
                hc[2 * m4 + 0] = fma2(w.x, qk2, hc[2 * m4 + 0]);
                hc[2 * m4 + 1] = fma2(w.y, qk2, hc[2 * m4 + 1]);
            }
        }

        // ---- fused exact GELU + stats + GEMM2 (hc[m] dies immediately) ----
        #pragma unroll
        for (int m = 0; m < 16; ++m) {
            float a, b;
            unpack2(hc[m], a, b);
            a = a * normcdff(a);               // exact-erf GELU
            b = b * normcdff(b);
            const u64 g2v = pack2(a, b);
            sum2 = add2(sum2, g2v);
            sq2  = fma2(g2v, g2v, sq2);

            const int h = c * 32 + 2 * m;
            const u64 a2 = pack2(a, a);
            const u64 b2v = pack2(b, b);
            const ulonglong2* wa = (const ulonglong2*)(sW2g + (h + 0) * NB);
            const ulonglong2* wb = (const ulonglong2*)(sW2g + (h + 1) * NB);
            #pragma unroll
            for (int n4 = 0; n4 < NB / 4; ++n4) {
                ulonglong2 w = wa[n4];
                S[2 * n4 + 0] = fma2(w.x, a2, S[2 * n4 + 0]);
                S[2 * n4 + 1] = fma2(w.y, a2, S[2 * n4 + 1]);
            }
            #pragma unroll
            for (int n4 = 0; n4 < NB / 4; ++n4) {
                ulonglong2 w = wb[n4];
                S[2 * n4 + 0] = fma2(w.x, b2v, S[2 * n4 + 0]);
                S[2 * n4 + 1] = fma2(w.y, b2v, S[2 * n4 + 1]);
            }
        }
    }

    // ---- finalize: mu, rstd, epilogue constants ----
    float slo, shi, qlo, qhi;
    unpack2(sum2, slo, shi);
    unpack2(sq2,  qlo, qhi);
    const float mu   = (slo + shi) * (1.0f / H);
    const float ex2  = (qlo + qhi) * (1.0f / H);
    const float var  = ex2 - mu * mu;
    const float rstd = rsqrtf(var + 1e-5f);

    const u64 r2   = pack2(rstd, rstd);
    const u64 nmr2 = pack2(-rstd * mu, -rstd * mu);
    const u64* c12 = (const u64*)sC1;
    const u64* c22 = (const u64*)sC2;

    ulonglong2* op = (ulonglong2*)(out + ((size_t)(i0 + ty) * L + (j0 + tx)) * NB);
    #pragma unroll
    for (int n4 = 0; n4 < NB / 4; ++n4) {
        u64 t0 = fma2(S[2 * n4 + 0], r2, c22[2 * n4 + 0]);
        u64 t1 = fma2(S[2 * n4 + 1], r2, c22[2 * n4 + 1]);
        ulonglong2 v;
        v.x = fma2(c12[2 * n4 + 0], nmr2, t0);
        v.y = fma2(c12[2 * n4 + 1], nmr2, t1);
        op[n4] = v;
    }
}

static const int MAIN_SMEM_BYTES =
    (DP2 * H + H * NB + TJ * QK_PITCH + TI * QK_PITCH +
     TJ * A_PITCH + TI * A_PITCH + NB + NB) * (int)sizeof(float);

extern "C" void kernel_launch(void* const* d_in, const int* in_sizes, int n_in,
                              void* d_out, int out_size) {
    const float* x   = (const float*)d_in[0];
    const float* Wd  = (const float*)d_in[1];
    const float* bd  = (const float*)d_in[2];
    const float* W1  = (const float*)d_in[3];
    const float* b1  = (const float*)d_in[4];
    const float* lng = (const float*)d_in[5];
    const float* lnb = (const float*)d_in[6];
    const float* W2  = (const float*)d_in[7];
    const float* b2  = (const float*)d_in[8];
    float* out = (float*)d_out;

    cudaFuncSetAttribute(main_kernel,
                         cudaFuncAttributeMaxDynamicSharedMemorySize,
                         MAIN_SMEM_BYTES);

    pre_kernel<<<97, 256>>>(x, Wd, bd, W1, b1, lng, lnb, W2, b2);
    main_kernel<<<dim3(L / TJ, L / TI), 256, MAIN_SMEM_BYTES>>>(W1, out);
}

// round 11
// speedup vs baseline: 2.0713x; 1.8439x over previous
#include <cuda_runtime.h>
#include <math.h>

#define L   768
#define D   1024
#define DP  128
#define DP2 64
#define H   128
#define NB  64

#define TJ 16          // j per tile
#define TI 8           // i per tile
#define NPAIR 128      // pairs per CTA
#define GPITCH 130     // sG row pitch (even -> 8B-aligned u64 slots)

typedef unsigned long long u64;

// ---- packed f32x2 helpers ----
__device__ __forceinline__ u64 pack2(float lo, float hi) {
    u64 r; asm("mov.b64 %0, {%1,%2};" : "=l"(r) : "f"(lo), "f"(hi)); return r;
}
__device__ __forceinline__ void unpack2(u64 v, float& lo, float& hi) {
    asm("mov.b64 {%0,%1}, %2;" : "=f"(lo), "=f"(hi) : "l"(v));
}
__device__ __forceinline__ u64 fma2(u64 a, u64 b, u64 c) {
    u64 d; asm("fma.rn.f32x2 %0, %1, %2, %3;" : "=l"(d) : "l"(a), "l"(b), "l"(c)); return d;
}
__device__ __forceinline__ u64 add2(u64 a, u64 b) {
    u64 d; asm("add.rn.f32x2 %0, %1, %2;" : "=l"(d) : "l"(a), "l"(b)); return d;
}
__device__ __forceinline__ u64 mul2(u64 a, u64 b) {
    u64 d; asm("mul.rn.f32x2 %0, %1, %2;" : "=l"(d) : "l"(a), "l"(b)); return d;
}

// ---- device scratch (transposed layouts for conflict-free staging) ----
__device__ float g_qT  [DP2 * L];    // [p][l]
__device__ float g_kT  [DP2 * L];    // [p][l]
__device__ float g_AqT [H * L];      // [h][l] = q[l]@W1b[h]+b1[h]
__device__ float g_AkT [H * L];      // [h][l] = k[l]@W1b[h]
__device__ float g_W1aT[DP2 * H];    // [p][h] = W1[h][p], p<64
__device__ float g_W2g [H * NB];     // [h][n] = W2[n,h]*ln_g[h]
__device__ float g_c1  [NB];
__device__ float g_c2  [NB];

// ============================================================
// Kernel 0 (blocks 0..95): down-projection + additive terms, 8 rows/CTA,
// writing TRANSPOSED outputs coalesced via smem staging.
// Block 96: epilogue constants + W1a transpose.
// ============================================================
__global__ void __launch_bounds__(256, 1)
pre_kernel(const float* __restrict__ x,
           const float* __restrict__ Wd,
           const float* __restrict__ bd,
           const float* __restrict__ W1,
           const float* __restrict__ b1,
           const float* __restrict__ lng,
           const float* __restrict__ lnb,
           const float* __restrict__ W2,
           const float* __restrict__ b2) {
    const int tid = threadIdx.x;

    if (blockIdx.x == 96) {
        for (int idx = tid; idx < H * NB; idx += 256) {
            int h = idx >> 6;
            int n = idx & 63;
            g_W2g[idx] = W2[n * H + h] * lng[h];
        }
        for (int idx = tid; idx < DP2 * H; idx += 256) {
            int p = idx >> 7;
            int h = idx & 127;
            g_W1aT[idx] = W1[h * DP + p];
        }
        if (tid < NB) {
            float c1 = 0.f, c2 = 0.f;
            for (int h = 0; h < H; ++h) {
                float w = W2[tid * H + h];
                c1 = fmaf(w, lng[h], c1);
                c2 = fmaf(w, lnb[h], c2);
            }
            g_c1[tid] = c1;
            g_c2[tid] = c2 + b2[tid];
        }
        return;
    }

    __shared__ float sx[8 * D];        // 32 KB, multiply reused
    const int l0   = blockIdx.x * 8;
    const int p    = tid & 127;
    const int half = tid >> 7;

    // stage 8 rows of x
    {
        const float4* xr  = (const float4*)(x + (size_t)l0 * D);
        float4*       sx4 = (float4*)sx;
        #pragma unroll
        for (int it = 0; it < 8; ++it) sx4[tid + it * 256] = xr[tid + it * 256];
    }
    __syncthreads();

    // down-projection: thread (p, half) -> rows half*4..+3
    float acc0 = bd[p], acc1 = acc0, acc2 = acc0, acc3 = acc0;
    {
        const float4* wr  = (const float4*)(Wd + (size_t)p * D);
        const float4* sx4 = (const float4*)(sx + (half * 4) * D);
        #pragma unroll 4
        for (int i = 0; i < D / 4; ++i) {
            float4 w = wr[i];
            float4 a = sx4[i];
            float4 b = sx4[i + 1 * (D / 4)];
            float4 c = sx4[i + 2 * (D / 4)];
            float4 d = sx4[i + 3 * (D / 4)];
            acc0 = fmaf(w.x, a.x, acc0); acc0 = fmaf(w.y, a.y, acc0);
            acc0 = fmaf(w.z, a.z, acc0); acc0 = fmaf(w.w, a.w, acc0);
            acc1 = fmaf(w.x, b.x, acc1); acc1 = fmaf(w.y, b.y, acc1);
            acc1 = fmaf(w.z, b.z, acc1); acc1 = fmaf(w.w, b.w, acc1);
            acc2 = fmaf(w.x, c.x, acc2); acc2 = fmaf(w.y, c.y, acc2);
            acc2 = fmaf(w.z, c.z, acc2); acc2 = fmaf(w.w, c.w, acc2);
            acc3 = fmaf(w.x, d.x, acc3); acc3 = fmaf(w.y, d.y, acc3);
            acc3 = fmaf(w.z, d.z, acc3); acc3 = fmaf(w.w, d.w, acc3);
        }
    }
    float accs[4] = {acc0, acc1, acc2, acc3};
    __syncthreads();
    // xd into sx[0..1023] (x fully consumed)
    #pragma unroll
    for (int r = 0; r < 4; ++r) sx[(half * 4 + r) * DP + p] = accs[r];
    __syncthreads();

    // additive terms: thread (h, half)
    const int h = tid & 127;
    float aq[4], ak[4];
    {
        const float* w  = W1 + (size_t)h * DP + DP2;
        const float* xd = sx + (half * 4) * DP;
        #pragma unroll
        for (int r = 0; r < 4; ++r) { aq[r] = b1[h]; ak[r] = 0.f; }
        #pragma unroll 4
        for (int pp = 0; pp < DP2; ++pp) {
            float wv = w[pp];
            #pragma unroll
            for (int r = 0; r < 4; ++r) {
                aq[r] = fmaf(wv, xd[r * DP + pp],       aq[r]);
                ak[r] = fmaf(wv, xd[r * DP + DP2 + pp], ak[r]);
            }
        }
    }
    __syncthreads();

    // stage transposes into sx:
    //   aqS [h:128][rr:8] @0 , akS @1024 , qS [p:64][rr:8] @2048 , kS @2560
    {
        float* aqS = sx;
        float* akS = sx + 1024;
        float* qS  = sx + 2048;
        float* kS  = sx + 2560;
        #pragma unroll
        for (int r = 0; r < 4; ++r) {
            aqS[h * 8 + half * 4 + r] = aq[r];
            akS[h * 8 + half * 4 + r] = ak[r];
            if (p < DP2) qS[p * 8 + half * 4 + r]         = accs[r];
            else         kS[(p - DP2) * 8 + half * 4 + r] = accs[r];
        }
    }
    __syncthreads();

    // coalesced transposed writes
    for (int idx = tid; idx < H * 8; idx += 256) {
        int hh = idx >> 3;
        int rr = idx & 7;
        g_AqT[hh * L + l0 + rr] = sx[idx];
        g_AkT[hh * L + l0 + rr] = sx[1024 + idx];
    }
    for (int idx = tid; idx < DP2 * 8; idx += 256) {
        int pp = idx >> 3;
        int rr = idx & 7;
        g_qT[pp * L + l0 + rr] = sx[2048 + idx];
        g_kT[pp * L + l0 + rr] = sx[2560 + idx];
    }
}

// ============================================================
// Main kernel: CTA = 128 pairs (16 j x 8 i), 256 threads, 2 CTAs/SM.
// Thread pair-ownership is STRIDED: u64-slot us = s*16 + pg (s=0..3),
// pairs {2*us, 2*us+1} -> every smem access instruction covers 128B of
// consecutive banks (conflict-free, wavefront floor).
// Phase 1: GEMM1 (on-the-fly qk; k staged lane-duplicated) + GELU -> sG
// Stats:   split-half partial sums -> per-pair mu/rstd
// Phase 2: GEMM2, LN folded into epilogue constants c1/c2.
// ============================================================
extern __shared__ float smem[];

__global__ void __launch_bounds__(256, 2)
main_kernel(float* __restrict__ out) {
    float* sW   = smem;                  // 8192: ph1 W1aT [p][h]; ph2 W2g [h][n]
    float* sG   = sW   + DP2 * H;        // [h:128][GPITCH]  16640
    float* sqT  = sG   + H * GPITCH;     // [p:64][j:16]     1024
    float* skTd = sqT  + DP2 * TJ;       // u64 [p:64][i:8]  1024 floats (dup lanes)
    float* sMu  = skTd + DP2 * TI * 2;   // 128
    float* sRs  = sMu  + NPAIR;          // 128
    float* sC1  = sRs  + NPAIR;          // 64
    float* sC2  = sC1  + NB;             // 64
    float* sPS  = sC2  + NB;             // 256
    float* sPQ  = sPS  + 256;            // 256

    const int tid = threadIdx.x;
    const int j0  = blockIdx.x * TJ;
    const int i0  = blockIdx.y * TI;

    // ---- stage (all coalesced) ----
    for (int idx = tid; idx < DP2 * H; idx += 256) sW[idx] = g_W1aT[idx];
    for (int idx = tid; idx < DP2 * TJ; idx += 256) {
        int p = idx >> 4;
        int j = idx & 15;
        sqT[idx] = g_qT[p * L + j0 + j];
    }
    for (int idx = tid; idx < DP2 * TI; idx += 256) {
        int p = idx >> 3;
        int i = idx & 7;
        float kv = g_kT[p * L + i0 + i];
        ((u64*)skTd)[idx] = pack2(kv, kv);      // lane-duplicated
    }
    if (tid < NB)           sC1[tid]      = g_c1[tid];
    else if (tid < 2 * NB)  sC2[tid - NB] = g_c2[tid - NB];
    __syncthreads();

    const int pg  = tid & 15;       // pair-group
    const int hg  = tid >> 4;       // h-group: h = hg*8..+7
    const int pgh = pg >> 3;        // 0/1: i-offset parity
    const int jl  = (2 * pg) & 15;  // even j of this thread's pair-lanes

    // =============== Phase 1: GEMM1 + GELU ===============
    {
        u64 hc[8][4];   // [hh][s]: pairs (32s+2pg, +1)
        #pragma unroll
        for (int hh = 0; hh < 8; ++hh) {
            const int h = hg * 8 + hh;
            const u64 aq2 = *(const u64*)(g_AqT + (size_t)h * L + j0 + jl);
            #pragma unroll
            for (int s = 0; s < 4; ++s) {
                float ak = g_AkT[(size_t)h * L + i0 + 2 * s + pgh];
                hc[hh][s] = add2(aq2, pack2(-ak, -ak));
            }
        }

        const u64* kd = (const u64*)skTd;
        #pragma unroll 2
        for (int p = 0; p < DP2; ++p) {
            const u64 q2 = *(const u64*)(sqT + p * TJ + jl);
            u64 qk[4];
            #pragma unroll
            for (int s = 0; s < 4; ++s)
                qk[s] = mul2(q2, kd[p * TI + 2 * s + pgh]);   // broadcast LDS.64
            const float4* w4 = (const float4*)(sW + p * H + hg * 8);
            float4 wA = w4[0];
            float4 wB = w4[1];
            const float wv[8] = {wA.x, wA.y, wA.z, wA.w, wB.x, wB.y, wB.z, wB.w};
            #pragma unroll
            for (int hh = 0; hh < 8; ++hh) {
                u64 w2 = pack2(wv[hh], wv[hh]);
                hc[hh][0] = fma2(qk[0], w2, hc[hh][0]);
                hc[hh][1] = fma2(qk[1], w2, hc[hh][1]);
                hc[hh][2] = fma2(qk[2], w2, hc[hh][2]);
                hc[hh][3] = fma2(qk[3], w2, hc[hh][3]);
            }
        }

        // exact GELU -> sG (strided u64 slots: conflict-free)
        #pragma unroll
        for (int hh = 0; hh < 8; ++hh) {
            const int h = hg * 8 + hh;
            #pragma unroll
            for (int s = 0; s < 4; ++s) {
                float a, b;
                unpack2(hc[hh][s], a, b);
                a = a * normcdff(a);
                b = b * normcdff(b);
                *(u64*)(sG + h * GPITCH + 2 * (s * 16 + pg)) = pack2(a, b);
            }
        }
    }
    __syncthreads();

    // ---- restage sW <- W2g, and split-half stats partials ----
    for (int idx = tid; idx < H * NB; idx += 256) sW[idx] = g_W2g[idx];
    {
        const int pair = tid & 127;
        const int hb   = tid >> 7;
        float s = 0.f, s2 = 0.f;
        #pragma unroll 8
        for (int h = hb * 64; h < hb * 64 + 64; ++h) {
            float v = sG[h * GPITCH + pair];
            s  += v;
            s2  = fmaf(v, v, s2);
        }
        sPS[tid] = s;
        sPQ[tid] = s2;
    }
    __syncthreads();
    if (tid < NPAIR) {
        float s   = sPS[tid] + sPS[tid + 128];
        float s2  = sPQ[tid] + sPQ[tid + 128];
        float mu  = s * (1.0f / H);
        float var = s2 * (1.0f / H) - mu * mu;
        sMu[tid] = mu;
        sRs[tid] = rsqrtf(var + 1e-5f);
    }
    __syncthreads();

    // =============== Phase 2: GEMM2 + epilogue ===============
    {
        const int pg2 = tid & 15;
        const int ng  = tid >> 4;      // n = ng*4..+3

        u64 S[4][4];                   // [n][s]
        #pragma unroll
        for (int n = 0; n < 4; ++n)
            #pragma unroll
            for (int s = 0; s < 4; ++s) S[n][s] = 0ULL;

        #pragma unroll 2
        for (int h = 0; h < H; ++h) {
            u64 g0 = *(const u64*)(sG + h * GPITCH + 2 * (0 * 16 + pg2));
            u64 g1 = *(const u64*)(sG + h * GPITCH + 2 * (1 * 16 + pg2));
            u64 g2 = *(const u64*)(sG + h * GPITCH + 2 * (2 * 16 + pg2));
            u64 g3 = *(const u64*)(sG + h * GPITCH + 2 * (3 * 16 + pg2));
            float4 wv = *(const float4*)(sW + h * NB + ng * 4);
            const float ws[4] = {wv.x, wv.y, wv.z, wv.w};
            #pragma unroll
            for (int n = 0; n < 4; ++n) {
                u64 w2 = pack2(ws[n], ws[n]);
                S[n][0] = fma2(g0, w2, S[n][0]);
                S[n][1] = fma2(g1, w2, S[n][1]);
                S[n][2] = fma2(g2, w2, S[n][2]);
                S[n][3] = fma2(g3, w2, S[n][3]);
            }
        }

        const float c1v[4] = {sC1[ng * 4 + 0], sC1[ng * 4 + 1],
                              sC1[ng * 4 + 2], sC1[ng * 4 + 3]};
        const float c2v[4] = {sC2[ng * 4 + 0], sC2[ng * 4 + 1],
                              sC2[ng * 4 + 2], sC2[ng * 4 + 3]};

        #pragma unroll
        for (int s = 0; s < 4; ++s) {
            float lo[4], hi[4];
            #pragma unroll
            for (int n = 0; n < 4; ++n) unpack2(S[n][s], lo[n], hi[n]);
            #pragma unroll
            for (int lane = 0; lane < 2; ++lane) {
                const int pair = 32 * s + 2 * pg2 + lane;
                const int il   = pair >> 4;
                const int jlw  = pair & 15;
                const float rs = sRs[pair];
                const float av = -rs * sMu[pair];
                const float* sv = lane ? hi : lo;
                float4 o;
                o.x = fmaf(rs, sv[0], fmaf(av, c1v[0], c2v[0]));
                o.y = fmaf(rs, sv[1], fmaf(av, c1v[1], c2v[1]));
                o.z = fmaf(rs, sv[2], fmaf(av, c1v[2], c2v[2]));
                o.w = fmaf(rs, sv[3], fmaf(av, c1v[3], c2v[3]));
                *(float4*)(out + ((size_t)(i0 + il) * L + (j0 + jlw)) * NB + ng * 4) = o;
            }
        }
    }
}

static const int MAIN_SMEM_BYTES =
    (DP2 * H + H * GPITCH + DP2 * TJ + DP2 * TI * 2 +
     NPAIR + NPAIR + NB + NB + 256 + 256) * (int)sizeof(float);

extern "C" void kernel_launch(void* const* d_in, const int* in_sizes, int n_in,
                              void* d_out, int out_size) {
    const float* x   = (const float*)d_in[0];
    const float* Wd  = (const float*)d_in[1];
    const float* bd  = (const float*)d_in[2];
    const float* W1  = (const float*)d_in[3];
    const float* b1  = (const float*)d_in[4];
    const float* lng = (const float*)d_in[5];
    const float* lnb = (const float*)d_in[6];
    const float* W2  = (const float*)d_in[7];
    const float* b2  = (const float*)d_in[8];
    float* out = (float*)d_out;

    cudaFuncSetAttribute(main_kernel,
                         cudaFuncAttributeMaxDynamicSharedMemorySize,
                         MAIN_SMEM_BYTES);

    pre_kernel<<<97, 256>>>(x, Wd, bd, W1, b1, lng, lnb, W2, b2);
    main_kernel<<<dim3(L / TJ, L / TI), 256, MAIN_SMEM_BYTES>>>(out);
}